// round 9
// baseline (speedup 1.0000x reference)
#include <cuda_runtime.h>
#include <cstdint>

#define B_SZ   2048
#define T_SZ   60
#define F_SZ   89
#define H_SZ   1024
#define OUT_SZ 30
#define NCH    35        // k-chunks of 32: 32 (h) + 3 (x, 89->96 padded)
#define HCHN   32
#define STAGES 3
#define STG_U32 8192     // 32KB per stage in uint32 units (A 4096 | B 4096)

// ---------------- persistent scratch (__device__ globals, no allocs) --------
__device__ __align__(16) uint32_t g_ap0[128 * 128 * 32 * 4];
__device__ __align__(16) uint32_t g_ap1[128 * 128 * 32 * 4];
__device__ __align__(16) uint32_t g_bp[32 * 70 * 2 * 8 * 32 * 4];
__device__ __align__(16) uint32_t g_xp[60 * 128 * 12 * 32 * 4];
__device__ float g_c [B_SZ * H_SZ];
__device__ float g_hl[B_SZ * H_SZ];
__device__ volatile int g_cnt[16 * 64];   // arrivals per (bx, t)

__device__ __forceinline__ uint32_t f2tf(float v) {
    uint32_t u;
    asm("cvt.rna.tf32.f32 %0, %1;" : "=r"(u) : "f"(v));
    return u;
}

__device__ __forceinline__ void mma_tf32(float (&d)[4], const uint4& a,
                                         uint32_t b0, uint32_t b1) {
    asm volatile(
        "mma.sync.aligned.m16n8k8.row.col.f32.tf32.tf32.f32 "
        "{%0,%1,%2,%3}, {%4,%5,%6,%7}, {%8,%9}, {%0,%1,%2,%3};"
        : "+f"(d[0]), "+f"(d[1]), "+f"(d[2]), "+f"(d[3])
        : "r"(a.x), "r"(a.y), "r"(a.z), "r"(a.w), "r"(b0), "r"(b1));
}

__device__ __forceinline__ void cp_async16(uint32_t saddr, const void* g) {
    asm volatile("cp.async.cg.shared.global [%0], [%1], 16;\n"
                 :: "r"(saddr), "l"(g));
}

// ---------------- prep kernels (run once per launch) ------------------------
__global__ void zero_state() {
    const int n = B_SZ * H_SZ;
    for (int i = blockIdx.x * blockDim.x + threadIdx.x; i < n;
         i += gridDim.x * blockDim.x) {
        g_c[i]   = 0.f;
        g_ap0[i] = 0u;
    }
    int gi = blockIdx.x * blockDim.x + threadIdx.x;
    if (gi < 16 * 64) g_cnt[gi] = 0;
}

__global__ void pack_B(const float* __restrict__ U, const float* __restrict__ W) {
    int idx = blockIdx.x * 256 + threadIdx.x;          // 32*143360 exact
    int by  = idx / 143360;
    int r   = idx % 143360;
    int c   = r / 2048;
    int r2  = r & 2047;
    int k8  = r2 >> 10;
    int g   = (r2 >> 7) & 7;
    int lane = (r2 >> 2) & 31;
    int v    = r2 & 3;
    int k    = c * 16 + k8 * 8 + (lane & 3) + (v & 1) * 4;
    int ncat = g * 16 + (v >> 1) * 8 + (lane >> 2);
    int col  = (ncat >> 5) * H_SZ + by * 32 + (ncat & 31);
    float val = 0.f;
    if (k < H_SZ)              val = U[k * (4 * H_SZ) + col];
    else if (k < H_SZ + F_SZ)  val = W[(k - H_SZ) * (4 * H_SZ) + col];
    g_bp[idx] = f2tf(val);
}

__global__ void pack_x(const float* __restrict__ x) {
    int idx = blockIdx.x * 256 + threadIdx.x;          // 60*196608 exact
    int t   = idx / 196608;
    int r   = idx % 196608;
    int mt  = r / 1536;
    int r2  = r % 1536;
    int k8  = r2 >> 7;
    int lane = (r2 >> 2) & 31;
    int v    = r2 & 3;
    int row  = mt * 16 + (lane >> 2) + (v & 1) * 8;
    int k    = k8 * 8 + (lane & 3) + (v >> 1) * 4;
    float val = (k < F_SZ) ? x[(row * T_SZ + t) * F_SZ + k] : 0.f;
    g_xp[idx] = f2tf(val);
}

// ---------------- persistent recurrent kernel -------------------------------
// 256 all-resident CTAs; CTA id owns tiles (id/32, id%32) and (id/32+8, id%32).
// Cross-CTA step dependency via g_cnt[bx][t] arrival counters.
__global__ __launch_bounds__(256, 2)
void lstm_persist(const float* __restrict__ bias) {
    extern __shared__ __align__(16) uint32_t smdyn[];   // STAGES * 32KB
    float (*zs)[132] = (float (*)[132])smdyn;           // epilogue alias

    const int tid = threadIdx.x, lane = tid & 31, warp = tid >> 5;
    const int warpM = warp >> 1, warpN = warp & 1;
    const uint32_t sbase = (uint32_t)__cvta_generic_to_shared(smdyn);
    const uint32_t sdst  = sbase + tid * 16;

    for (int t = 0; t < T_SZ; t++) {
        const uint32_t* __restrict__ ap = (t & 1) ? g_ap1 : g_ap0;
        uint32_t*       __restrict__ an = (t & 1) ? g_ap0 : g_ap1;

        for (int s2 = 0; s2 < 2; s2++) {
            const int vt = blockIdx.x + s2 * 256;
            const int bx = vt >> 5, by = vt & 31;
            const int mtB = bx * 8;

            // ---- wait for group bx, step t-1 to fully commit ----
            if (t > 0 && tid == 0) {
                while (g_cnt[bx * 64 + (t - 1)] < 32) { }
            }
            __syncthreads();

            // ---- per-tile copy offsets ----
            int aoffH[4], aoffX[4];
#pragma unroll
            for (int it = 0; it < 4; it++) {
                int idx = tid + it * 256;
                int b   = idx >> 5;              // 0..31
                int off = idx & 31;              // 16B units within 512B block
                int mtl = b >> 2, k8 = b & 3;
                aoffH[it] = (mtB + mtl) * 16384 + k8 * 128 + off * 4;
                aoffX[it] = (t * 128 + mtB + mtl) * 1536 + k8 * 128 + off * 4;
            }
            const uint32_t* bThr = g_bp + by * 143360 + tid * 4;

            auto issue = [&](int c, int s) {
                uint32_t sb = sdst + s * 32768;
                if (c < HCHN) {
                    int adv = c * 512;
#pragma unroll
                    for (int it = 0; it < 4; it++)
                        cp_async16(sb + it * 4096, ap + aoffH[it] + adv);
                } else {
                    int adv = (c - HCHN) * 512;
#pragma unroll
                    for (int it = 0; it < 4; it++)
                        cp_async16(sb + it * 4096, g_xp + aoffX[it] + adv);
                }
                const uint32_t* bsrc = bThr + c * 4096;
#pragma unroll
                for (int it = 0; it < 4; it++)
                    cp_async16(sb + 16384 + it * 4096, bsrc + it * 1024);
            };

            float acc[2][8][4] = {};

#pragma unroll
            for (int s = 0; s < STAGES - 1; s++) {
                issue(s, s);
                asm volatile("cp.async.commit_group;");
            }

            int stage = 0;
            for (int c = 0; c < NCH; c++) {
                asm volatile("cp.async.wait_group %0;" :: "n"(STAGES - 2));
                __syncthreads();

                const uint32_t* sA = smdyn + stage * STG_U32;
                const uint32_t* sB = sA + 4096;
#pragma unroll
                for (int k8 = 0; k8 < 4; k8++) {
                    uint4 aF[2];
#pragma unroll
                    for (int mi = 0; mi < 2; mi++)
                        aF[mi] = *(const uint4*)
                            &sA[((warpM * 2 + mi) * 4 + k8) * 128 + lane * 4];
#pragma unroll
                    for (int n2 = 0; n2 < 4; n2++) {
                        uint4 b = *(const uint4*)
                            &sB[k8 * 1024 + (warpN * 4 + n2) * 128 + lane * 4];
#pragma unroll
                        for (int mi = 0; mi < 2; mi++) {
                            mma_tf32(acc[mi][n2 * 2],     aF[mi], b.x, b.y);
                            mma_tf32(acc[mi][n2 * 2 + 1], aF[mi], b.z, b.w);
                        }
                    }
                }

                int cn = c + STAGES - 1;
                if (cn < NCH) issue(cn, cn % STAGES);
                asm volatile("cp.async.commit_group;");
                if (++stage == STAGES) stage = 0;
            }
            __syncthreads();   // pipe buffers dead; zs aliases them

            // ---- fused gate epilogue (two 64-row halves through shared) ----
#pragma unroll
            for (int half = 0; half < 2; half++) {
                if ((warpM >> 1) == half) {
#pragma unroll
                    for (int mi = 0; mi < 2; mi++) {
                        int zr = (warpM & 1) * 32 + mi * 16 + (lane >> 2);
#pragma unroll
                        for (int ni = 0; ni < 8; ni++) {
                            int cN = warpN * 64 + ni * 8 + (lane & 3) * 2;
                            zs[zr][cN]         = acc[mi][ni][0];
                            zs[zr][cN + 1]     = acc[mi][ni][1];
                            zs[zr + 8][cN]     = acc[mi][ni][2];
                            zs[zr + 8][cN + 1] = acc[mi][ni][3];
                        }
                    }
                }
                __syncthreads();
#pragma unroll
                for (int e = 0; e < 8; e++) {
                    int idx = tid + e * 256;          // 64*32 elems
                    int m  = idx >> 5, nl = idx & 31;
                    int gm = bx * 128 + half * 64 + m;
                    int hc = by * 32 + nl;
                    float zi = zs[m][nl]      + bias[hc];
                    float zf = zs[m][32 + nl] + bias[H_SZ + hc];
                    float zg = zs[m][64 + nl] + bias[2 * H_SZ + hc];
                    float zo = zs[m][96 + nl] + bias[3 * H_SZ + hc];
                    float ig = 1.f / (1.f + __expf(-zi));
                    float fg = 1.f / (1.f + __expf(-zf));
                    float gg = fmaxf(zg, 0.f);
                    float og = 1.f / (1.f + __expf(-zo));
                    int   ci = gm * H_SZ + hc;
                    float cn = fg * g_c[ci] + ig * gg;
                    g_c[ci] = cn;
                    float h = og * fmaxf(cn, 0.f);
                    // write h straight into next step's fragment layout
                    int mt = gm >> 4, rr = gm & 15, k8 = hc >> 3, kk = hc & 7;
                    int lw = (rr & 7) * 4 + (kk & 3);
                    int v  = ((kk >> 2) << 1) | (rr >> 3);
                    an[mt * 16384 + k8 * 128 + lw * 4 + v] = f2tf(h);
                    if (t == T_SZ - 1) g_hl[ci] = h;
                }
                __syncthreads();
            }

            // ---- signal arrival: all our stores device-visible first ----
            __threadfence();
            __syncthreads();
            if (tid == 0) atomicAdd((int*)&g_cnt[bx * 64 + t], 1);
        }
    }
}

// ---------------- dense head: y = h_T @ Wd + bd -----------------------------
__global__ void head_kernel(const float* __restrict__ Wd,
                            const float* __restrict__ bd,
                            float* __restrict__ out) {
    __shared__ float hs[H_SZ];
    const int row  = blockIdx.x;
    const int tid  = threadIdx.x;
    const int lane = tid & 31;
    const int w    = tid >> 5;
    for (int i = tid; i < H_SZ; i += 256) hs[i] = g_hl[row * H_SZ + i];
    __syncthreads();
    for (int o = w; o < OUT_SZ; o += 8) {
        float s = 0.f;
        for (int k = lane; k < H_SZ; k += 32) s += hs[k] * Wd[k * OUT_SZ + o];
#pragma unroll
        for (int off = 16; off; off >>= 1)
            s += __shfl_down_sync(0xffffffffu, s, off);
        if (lane == 0) out[row * OUT_SZ + o] = s + bd[o];
    }
}

extern "C" void kernel_launch(void* const* d_in, const int* in_sizes, int n_in,
                              void* d_out, int out_size) {
    const float* x    = (const float*)d_in[0];   // [2048,60,89]
    const float* W    = (const float*)d_in[1];   // [89,4096]
    const float* U    = (const float*)d_in[2];   // [1024,4096]
    const float* bias = (const float*)d_in[3];   // [4096]
    const float* Wd   = (const float*)d_in[4];   // [1024,30]
    const float* bd   = (const float*)d_in[5];   // [30]
    float* out = (float*)d_out;                  // [2048,30,1]

    static bool attr_set = false;
    if (!attr_set) {
        cudaFuncSetAttribute(lstm_persist,
                             cudaFuncAttributeMaxDynamicSharedMemorySize,
                             STAGES * 32768);
        attr_set = true;
    }

    pack_B<<<17920, 256>>>(U, W);
    pack_x<<<46080, 256>>>(x);
    zero_state<<<4096, 256>>>();

    lstm_persist<<<256, 256, STAGES * 32768>>>(bias);

    head_kernel<<<B_SZ, 256>>>(Wd, bd, out);
}

// round 10
// speedup vs baseline: 1.1076x; 1.1076x over previous
#include <cuda_runtime.h>
#include <cstdint>

#define B_SZ   2048
#define T_SZ   60
#define F_SZ   89
#define H_SZ   1024
#define OUT_SZ 30
#define NCH    35        // k-chunks of 32: 32 (h) + 3 (x, 89->96 padded)
#define HCHN   32
#define STAGES 3
#define STG_U32 8192     // 32KB per stage in uint32 units (A 4096 | B 4096)

// ---------------- persistent scratch (__device__ globals, no allocs) --------
__device__ __align__(16) uint32_t g_ap0[128 * 128 * 32 * 4];
__device__ __align__(16) uint32_t g_ap1[128 * 128 * 32 * 4];
__device__ __align__(16) uint32_t g_bp[32 * 70 * 2 * 8 * 32 * 4];
__device__ __align__(16) uint32_t g_xp[60 * 128 * 12 * 32 * 4];
__device__ float g_c [B_SZ * H_SZ];
__device__ float g_hl[B_SZ * H_SZ];
__device__ volatile int g_cnt[16 * 64];   // CTA arrivals per (bx, t), 16 each

__device__ __forceinline__ uint32_t f2tf(float v) {
    uint32_t u;
    asm("cvt.rna.tf32.f32 %0, %1;" : "=r"(u) : "f"(v));
    return u;
}

__device__ __forceinline__ void mma_tf32(float (&d)[4], const uint4& a,
                                         uint32_t b0, uint32_t b1) {
    asm volatile(
        "mma.sync.aligned.m16n8k8.row.col.f32.tf32.tf32.f32 "
        "{%0,%1,%2,%3}, {%4,%5,%6,%7}, {%8,%9}, {%0,%1,%2,%3};"
        : "+f"(d[0]), "+f"(d[1]), "+f"(d[2]), "+f"(d[3])
        : "r"(a.x), "r"(a.y), "r"(a.z), "r"(a.w), "r"(b0), "r"(b1));
}

__device__ __forceinline__ void cp_async16(uint32_t saddr, const void* g) {
    asm volatile("cp.async.cg.shared.global [%0], [%1], 16;\n"
                 :: "r"(saddr), "l"(g));
}

// ---------------- prep kernels (run once per launch) ------------------------
__global__ void zero_state() {
    const int n = B_SZ * H_SZ;
    for (int i = blockIdx.x * blockDim.x + threadIdx.x; i < n;
         i += gridDim.x * blockDim.x) {
        g_c[i]   = 0.f;
        g_ap0[i] = 0u;
    }
    int gi = blockIdx.x * blockDim.x + threadIdx.x;
    if (gi < 16 * 64) g_cnt[gi] = 0;
}

__global__ void pack_B(const float* __restrict__ U, const float* __restrict__ W) {
    int idx = blockIdx.x * 256 + threadIdx.x;          // 32*143360 exact
    int by  = idx / 143360;
    int r   = idx % 143360;
    int c   = r / 2048;
    int r2  = r & 2047;
    int k8  = r2 >> 10;
    int g   = (r2 >> 7) & 7;
    int lane = (r2 >> 2) & 31;
    int v    = r2 & 3;
    int k    = c * 16 + k8 * 8 + (lane & 3) + (v & 1) * 4;
    int ncat = g * 16 + (v >> 1) * 8 + (lane >> 2);
    int col  = (ncat >> 5) * H_SZ + by * 32 + (ncat & 31);
    float val = 0.f;
    if (k < H_SZ)              val = U[k * (4 * H_SZ) + col];
    else if (k < H_SZ + F_SZ)  val = W[(k - H_SZ) * (4 * H_SZ) + col];
    g_bp[idx] = f2tf(val);
}

__global__ void pack_x(const float* __restrict__ x) {
    int idx = blockIdx.x * 256 + threadIdx.x;          // 60*196608 exact
    int t   = idx / 196608;
    int r   = idx % 196608;
    int mt  = r / 1536;
    int r2  = r % 1536;
    int k8  = r2 >> 7;
    int lane = (r2 >> 2) & 31;
    int v    = r2 & 3;
    int row  = mt * 16 + (lane >> 2) + (v & 1) * 8;
    int k    = k8 * 8 + (lane & 3) + (v >> 1) * 4;
    float val = (k < F_SZ) ? x[(row * T_SZ + t) * F_SZ + k] : 0.f;
    g_xp[idx] = f2tf(val);
}

// ---------------- persistent recurrent kernel -------------------------------
// 256 all-resident CTAs. CTA id -> chain bx = id>>4, tiles by = 2*(id&15)+{0,1}.
// Chains are closed sets of 16 CTAs -> independent skew across chains.
__global__ __launch_bounds__(256, 2)
void lstm_persist(const float* __restrict__ bias) {
    extern __shared__ __align__(16) uint32_t smdyn[];   // STAGES * 32KB
    float (*zs)[132] = (float (*)[132])smdyn;           // epilogue alias

    const int tid = threadIdx.x, lane = tid & 31, warp = tid >> 5;
    const int warpM = warp >> 1, warpN = warp & 1;
    const uint32_t sbase = (uint32_t)__cvta_generic_to_shared(smdyn);
    const uint32_t sdst  = sbase + tid * 16;

    const int bx  = blockIdx.x >> 4;          // chain id, 0..15
    const int byp = blockIdx.x & 15;          // by pair, tiles 2*byp, 2*byp+1
    const int mtB = bx * 8;

    // ---- A copy offsets: same for both tiles (same bx) -----------------
    int aoffH[4];
    int aX_b[4], aX_k[4];                     // xpack split: t-dep + fixed
#pragma unroll
    for (int it = 0; it < 4; it++) {
        int idx = tid + it * 256;
        int b   = idx >> 5;                   // 0..31
        int off = idx & 31;                   // 16B units within 512B block
        int mtl = b >> 2, k8 = b & 3;
        aoffH[it] = (mtB + mtl) * 16384 + k8 * 128 + off * 4;
        aX_b[it]  = (mtB + mtl) * 1536 + k8 * 128 + off * 4;
    }

    for (int t = 0; t < T_SZ; t++) {
        const uint32_t* __restrict__ ap = (t & 1) ? g_ap1 : g_ap0;
        uint32_t*       __restrict__ an = (t & 1) ? g_ap0 : g_ap1;
        const int xbase = t * 128 * 1536;

        // ---- wait: chain bx step t-1 fully committed (16 CTA arrivals) --
        if (t > 0) {
            if (tid == 0) {
                while (g_cnt[bx * 64 + (t - 1)] < 16) __nanosleep(128);
            }
            __syncthreads();
            __threadfence();                  // acquire before reading h
        }

        for (int s2 = 0; s2 < 2; s2++) {
            const int by = byp * 2 + s2;
            const uint32_t* bThr = g_bp + by * 143360 + tid * 4;

            auto issue = [&](int c, int s) {
                uint32_t sb = sdst + s * 32768;
                if (c < HCHN) {
                    int adv = c * 512;
#pragma unroll
                    for (int it = 0; it < 4; it++)
                        cp_async16(sb + it * 4096, ap + aoffH[it] + adv);
                } else {
                    int adv = xbase + (c - HCHN) * 512;
#pragma unroll
                    for (int it = 0; it < 4; it++)
                        cp_async16(sb + it * 4096, g_xp + aX_b[it] + adv);
                }
                const uint32_t* bsrc = bThr + c * 4096;
#pragma unroll
                for (int it = 0; it < 4; it++)
                    cp_async16(sb + 16384 + it * 4096, bsrc + it * 1024);
            };

            float acc[2][8][4] = {};

#pragma unroll
            for (int s = 0; s < STAGES - 1; s++) {
                issue(s, s);
                asm volatile("cp.async.commit_group;");
            }

            int stage = 0;
            for (int c = 0; c < NCH; c++) {
                asm volatile("cp.async.wait_group %0;" :: "n"(STAGES - 2));
                __syncthreads();

                const uint32_t* sA = smdyn + stage * STG_U32;
                const uint32_t* sB = sA + 4096;
#pragma unroll
                for (int k8 = 0; k8 < 4; k8++) {
                    uint4 aF[2];
#pragma unroll
                    for (int mi = 0; mi < 2; mi++)
                        aF[mi] = *(const uint4*)
                            &sA[((warpM * 2 + mi) * 4 + k8) * 128 + lane * 4];
#pragma unroll
                    for (int n2 = 0; n2 < 4; n2++) {
                        uint4 b = *(const uint4*)
                            &sB[k8 * 1024 + (warpN * 4 + n2) * 128 + lane * 4];
#pragma unroll
                        for (int mi = 0; mi < 2; mi++) {
                            mma_tf32(acc[mi][n2 * 2],     aF[mi], b.x, b.y);
                            mma_tf32(acc[mi][n2 * 2 + 1], aF[mi], b.z, b.w);
                        }
                    }
                }

                int cn = c + STAGES - 1;
                if (cn < NCH) issue(cn, cn % STAGES);
                asm volatile("cp.async.commit_group;");
                if (++stage == STAGES) stage = 0;
            }
            __syncthreads();   // pipe buffers dead; zs aliases them

            // ---- fused gate epilogue (two 64-row halves through shared) --
#pragma unroll
            for (int half = 0; half < 2; half++) {
                if ((warpM >> 1) == half) {
#pragma unroll
                    for (int mi = 0; mi < 2; mi++) {
                        int zr = (warpM & 1) * 32 + mi * 16 + (lane >> 2);
#pragma unroll
                        for (int ni = 0; ni < 8; ni++) {
                            int cN = warpN * 64 + ni * 8 + (lane & 3) * 2;
                            zs[zr][cN]         = acc[mi][ni][0];
                            zs[zr][cN + 1]     = acc[mi][ni][1];
                            zs[zr + 8][cN]     = acc[mi][ni][2];
                            zs[zr + 8][cN + 1] = acc[mi][ni][3];
                        }
                    }
                }
                __syncthreads();
#pragma unroll
                for (int e = 0; e < 8; e++) {
                    int idx = tid + e * 256;          // 64*32 elems
                    int m  = idx >> 5, nl = idx & 31;
                    int gm = bx * 128 + half * 64 + m;
                    int hc = by * 32 + nl;
                    float zi = zs[m][nl]      + bias[hc];
                    float zf = zs[m][32 + nl] + bias[H_SZ + hc];
                    float zg = zs[m][64 + nl] + bias[2 * H_SZ + hc];
                    float zo = zs[m][96 + nl] + bias[3 * H_SZ + hc];
                    float ig = 1.f / (1.f + __expf(-zi));
                    float fg = 1.f / (1.f + __expf(-zf));
                    float gg = fmaxf(zg, 0.f);
                    float og = 1.f / (1.f + __expf(-zo));
                    int   ci = gm * H_SZ + hc;
                    float cn = fg * g_c[ci] + ig * gg;
                    g_c[ci] = cn;
                    float h = og * fmaxf(cn, 0.f);
                    // write h straight into next step's fragment layout
                    int mt = gm >> 4, rr = gm & 15, k8 = hc >> 3, kk = hc & 7;
                    int lw = (rr & 7) * 4 + (kk & 3);
                    int v  = ((kk >> 2) << 1) | (rr >> 3);
                    an[mt * 16384 + k8 * 128 + lw * 4 + v] = f2tf(h);
                    if (t == T_SZ - 1) g_hl[ci] = h;
                }
                __syncthreads();
            }
        }

        // ---- signal: both tiles of this CTA committed for step t --------
        __threadfence();
        __syncthreads();
        if (tid == 0) atomicAdd((int*)&g_cnt[bx * 64 + t], 1);
    }
}

// ---------------- dense head: y = h_T @ Wd + bd -----------------------------
__global__ void head_kernel(const float* __restrict__ Wd,
                            const float* __restrict__ bd,
                            float* __restrict__ out) {
    __shared__ float hs[H_SZ];
    const int row  = blockIdx.x;
    const int tid  = threadIdx.x;
    const int lane = tid & 31;
    const int w    = tid >> 5;
    for (int i = tid; i < H_SZ; i += 256) hs[i] = g_hl[row * H_SZ + i];
    __syncthreads();
    for (int o = w; o < OUT_SZ; o += 8) {
        float s = 0.f;
        for (int k = lane; k < H_SZ; k += 32) s += hs[k] * Wd[k * OUT_SZ + o];
#pragma unroll
        for (int off = 16; off; off >>= 1)
            s += __shfl_down_sync(0xffffffffu, s, off);
        if (lane == 0) out[row * OUT_SZ + o] = s + bd[o];
    }
}

extern "C" void kernel_launch(void* const* d_in, const int* in_sizes, int n_in,
                              void* d_out, int out_size) {
    const float* x    = (const float*)d_in[0];   // [2048,60,89]
    const float* W    = (const float*)d_in[1];   // [89,4096]
    const float* U    = (const float*)d_in[2];   // [1024,4096]
    const float* bias = (const float*)d_in[3];   // [4096]
    const float* Wd   = (const float*)d_in[4];   // [1024,30]
    const float* bd   = (const float*)d_in[5];   // [30]
    float* out = (float*)d_out;                  // [2048,30,1]

    static bool attr_set = false;
    if (!attr_set) {
        cudaFuncSetAttribute(lstm_persist,
                             cudaFuncAttributeMaxDynamicSharedMemorySize,
                             STAGES * 32768);
        attr_set = true;
    }

    pack_B<<<17920, 256>>>(U, W);
    pack_x<<<46080, 256>>>(x);
    zero_state<<<4096, 256>>>();

    lstm_persist<<<256, 256, STAGES * 32768>>>(bias);

    head_kernel<<<B_SZ, 256>>>(Wd, bd, out);
}

// round 13
// speedup vs baseline: 1.9785x; 1.7864x over previous
#include <cuda_runtime.h>
#include <cuda_fp16.h>
#include <cstdint>

#define B_SZ   2048
#define T_SZ   60
#define F_SZ   89
#define H_SZ   1024
#define OUT_SZ 30
#define NCH    35        // k-chunks of 32: 32 (h) + 3 (x, 89->96 padded)
#define HCHN   32
#define STAGES 3
#define STG_U32 4096     // 16KB per stage in u32 units (A 8KB | B 8KB)

// ---------------- persistent scratch (__device__ globals, no allocs) --------
// Apack: h fp16 pairs, m16n8k16 A-frag order [mt(128)][k16(64)][lane(32)][v(4)]
__device__ __align__(16) uint32_t g_ap0[128 * 64 * 32 * 4];
__device__ __align__(16) uint32_t g_ap1[128 * 64 * 32 * 4];
// Bpack: U|W fp16 B-frags [by(32)][ch(35)][k16(2)][nb16(8)][lane(32)][v(4)]
__device__ __align__(16) uint32_t g_bp[32 * 35 * 2 * 8 * 32 * 4];
// xpack: x fp16 A-frags [t(60)][mt(128)][k16x(6)][lane(32)][v(4)]
__device__ __align__(16) uint32_t g_xp[60 * 128 * 6 * 32 * 4];
__device__ float g_c [B_SZ * H_SZ];
__device__ float g_hl[B_SZ * H_SZ];

__device__ __forceinline__ void mma_f16(float (&d)[4], const uint4& a,
                                        uint32_t b0, uint32_t b1) {
    asm volatile(
        "mma.sync.aligned.m16n8k16.row.col.f32.f16.f16.f32 "
        "{%0,%1,%2,%3}, {%4,%5,%6,%7}, {%8,%9}, {%0,%1,%2,%3};"
        : "+f"(d[0]), "+f"(d[1]), "+f"(d[2]), "+f"(d[3])
        : "r"(a.x), "r"(a.y), "r"(a.z), "r"(a.w), "r"(b0), "r"(b1));
}

__device__ __forceinline__ void cp_async16(uint32_t saddr, const void* g) {
    asm volatile("cp.async.cg.shared.global [%0], [%1], 16;\n"
                 :: "r"(saddr), "l"(g));
}

// ---------------- prep kernels (run once per launch) ------------------------
__global__ void zero_state() {
    int gi = blockIdx.x * blockDim.x + threadIdx.x;
    int stride = gridDim.x * blockDim.x;
    for (int i = gi; i < 128 * 64 * 32 * 4; i += stride) g_ap0[i] = 0u;
    for (int i = gi; i < B_SZ * H_SZ; i += stride)       g_c[i]  = 0.f;
}

// B-frag for m16n8k16 (col-major B = [K,N] with N = ncat gate strips):
// v = { n8lo klo, n8lo khi, n8hi klo, n8hi khi }, each u32 = fp16 pair (k, k+1)
__global__ void pack_B(const float* __restrict__ U, const float* __restrict__ W) {
    int idx = blockIdx.x * 256 + threadIdx.x;   // 32*71680 = 2,293,760 exact
    int by  = idx / 71680;
    int r   = idx % 71680;
    int ch  = r / 2048;
    int r2  = r & 2047;
    int k16 = r2 >> 10;
    int nb  = (r2 >> 7) & 7;
    int lane = (r2 >> 2) & 31;
    int v    = r2 & 3;
    int gid = lane >> 2, tig = lane & 3;
    int k    = ch * 32 + k16 * 16 + tig * 2 + (v & 1) * 8;
    int ncat = nb * 16 + (v >> 1) * 8 + gid;
    int uc   = (ncat >> 5) * H_SZ + by * 32 + (ncat & 31);
    float v0 = 0.f, v1 = 0.f;
    if (k < H_SZ)                 v0 = U[k * (4 * H_SZ) + uc];
    else if (k < H_SZ + F_SZ)     v0 = W[(k - H_SZ) * (4 * H_SZ) + uc];
    if (k + 1 < H_SZ)             v1 = U[(k + 1) * (4 * H_SZ) + uc];
    else if (k + 1 < H_SZ + F_SZ) v1 = W[(k + 1 - H_SZ) * (4 * H_SZ) + uc];
    __half2 h2 = __halves2half2(__float2half(v0), __float2half(v1));
    g_bp[idx] = *(uint32_t*)&h2;
}

// A-frag: v = { rlo klo, rhi klo, rlo khi, rhi khi }, u32 = fp16 pair (k, k+1)
__global__ void pack_x(const float* __restrict__ x) {
    int idx = blockIdx.x * 256 + threadIdx.x;   // 60*98304 = 5,898,240 exact
    int t   = idx / 98304;
    int r   = idx % 98304;
    int mt  = r / 768;
    int r2  = r % 768;
    int k16 = r2 >> 7;
    int lane = (r2 >> 2) & 31;
    int v    = r2 & 3;
    int gid = lane >> 2, tig = lane & 3;
    int row = mt * 16 + gid + (v & 1) * 8;
    int f   = k16 * 16 + tig * 2 + (v >> 1) * 8;
    float v0 = (f < F_SZ)     ? x[(row * T_SZ + t) * F_SZ + f]     : 0.f;
    float v1 = (f + 1 < F_SZ) ? x[(row * T_SZ + t) * F_SZ + f + 1] : 0.f;
    __half2 h2 = __halves2half2(__float2half(v0), __float2half(v1));
    g_xp[idx] = *(uint32_t*)&h2;
}

// ---------------- recurrent step: fp16 K32 cp.async pipelined GEMM ----------
__global__ __launch_bounds__(256, 2)
void lstm_step(const float* __restrict__ bias, int t) {
    const int bx = blockIdx.x, by = blockIdx.y;
    const int tid = threadIdx.x, lane = tid & 31, warp = tid >> 5;
    const int warpM = warp >> 1, warpN = warp & 1;

    const uint32_t* __restrict__ ap = (t & 1) ? g_ap1 : g_ap0;
    uint32_t*       __restrict__ an = (t & 1) ? g_ap0 : g_ap1;

    __shared__ __align__(16) union {
        uint32_t pipe[STAGES][STG_U32];   // [stage][ A:2048 | B:2048 ]
        float    zs[64][132];
    } sm;

    const int mtB = bx * 8;
    const uint32_t sbase = (uint32_t)__cvta_generic_to_shared(&sm.pipe[0][0]);
    const uint32_t sdst  = sbase + tid * 16;

    // ---- hoisted per-thread copy offsets (u32 element units) ----
    // A: 8 blocks (mt) of 1KB per stage; thread copies 2 x 16B.
    int aoffH[2], aoffX[2];
#pragma unroll
    for (int it = 0; it < 2; it++) {
        int idx = tid + it * 256;
        int b   = idx >> 6;              // 0..7 (mt local)
        int off = idx & 63;              // 16B units within 1KB block
        aoffH[it] = (mtB + b) * 8192 + off * 4;
        aoffX[it] = (t * 128 + mtB + b) * 768 + off * 4;
    }
    const uint32_t* bThr = g_bp + by * 71680 + tid * 4;   // + c*2048 + it*1024

    auto issue = [&](int c, int s) {
        uint32_t sb = sdst + s * 16384;
        if (c < HCHN) {
            int adv = c * 256;
#pragma unroll
            for (int it = 0; it < 2; it++)
                cp_async16(sb + it * 4096, ap + aoffH[it] + adv);
        } else {
            int adv = (c - HCHN) * 256;
#pragma unroll
            for (int it = 0; it < 2; it++)
                cp_async16(sb + it * 4096, g_xp + aoffX[it] + adv);
        }
        const uint32_t* bsrc = bThr + c * 2048;
#pragma unroll
        for (int it = 0; it < 2; it++)
            cp_async16(sb + 8192 + it * 4096, bsrc + it * 1024);
    };

    float acc[2][8][4] = {};

#pragma unroll
    for (int s = 0; s < STAGES - 1; s++) {
        issue(s, s);
        asm volatile("cp.async.commit_group;");
    }

    int stage = 0;
    for (int c = 0; c < NCH; c++) {
        asm volatile("cp.async.wait_group %0;" :: "n"(STAGES - 2));
        __syncthreads();

        const uint32_t* sA = sm.pipe[stage];          // [mtl(8)][k16(2)][lane][v]
        const uint32_t* sB = sA + 2048;               // [k16(2)][nb16(8)][lane][v]
#pragma unroll
        for (int k16 = 0; k16 < 2; k16++) {
            uint4 aF[2];
#pragma unroll
            for (int mi = 0; mi < 2; mi++)
                aF[mi] = *(const uint4*)
                    &sA[(warpM * 2 + mi) * 256 + k16 * 128 + lane * 4];
#pragma unroll
            for (int j = 0; j < 4; j++) {
                uint4 b = *(const uint4*)
                    &sB[k16 * 1024 + (warpN * 4 + j) * 128 + lane * 4];
#pragma unroll
                for (int mi = 0; mi < 2; mi++) {
                    mma_f16(acc[mi][j * 2],     aF[mi], b.x, b.y);
                    mma_f16(acc[mi][j * 2 + 1], aF[mi], b.z, b.w);
                }
            }
        }

        int cn = c + STAGES - 1;
        if (cn < NCH) issue(cn, cn % STAGES);
        asm volatile("cp.async.commit_group;");
        if (++stage == STAGES) stage = 0;
    }
    __syncthreads();   // pipe buffers dead; zs aliases them

    // ---- fused gate epilogue (two 64-row halves through shared) ----
#pragma unroll
    for (int half = 0; half < 2; half++) {
        if ((warpM >> 1) == half) {
#pragma unroll
            for (int mi = 0; mi < 2; mi++) {
                int zr = (warpM & 1) * 32 + mi * 16 + (lane >> 2);
#pragma unroll
                for (int ni = 0; ni < 8; ni++) {
                    int cN = warpN * 64 + ni * 8 + (lane & 3) * 2;
                    sm.zs[zr][cN]         = acc[mi][ni][0];
                    sm.zs[zr][cN + 1]     = acc[mi][ni][1];
                    sm.zs[zr + 8][cN]     = acc[mi][ni][2];
                    sm.zs[zr + 8][cN + 1] = acc[mi][ni][3];
                }
            }
        }
        __syncthreads();
        // pairs: 64 rows x 16 col-pairs = 1024 items, 4 per thread
#pragma unroll
        for (int e = 0; e < 4; e++) {
            int idx = tid + e * 256;
            int m  = idx >> 4, np = idx & 15;
            int nl = np * 2;
            int gm = bx * 128 + half * 64 + m;
            int hc = by * 32 + nl;
            float2 co = *(float2*)&g_c[gm * H_SZ + hc];
            float hv[2];
#pragma unroll
            for (int q = 0; q < 2; q++) {
                int nn = nl + q;
                float zi = sm.zs[m][nn]      + bias[hc + q];
                float zf = sm.zs[m][32 + nn] + bias[H_SZ + hc + q];
                float zg = sm.zs[m][64 + nn] + bias[2 * H_SZ + hc + q];
                float zo = sm.zs[m][96 + nn] + bias[3 * H_SZ + hc + q];
                float ig = 1.f / (1.f + __expf(-zi));
                float fg = 1.f / (1.f + __expf(-zf));
                float gg = fmaxf(zg, 0.f);
                float og = 1.f / (1.f + __expf(-zo));
                float cv = (q == 0) ? co.x : co.y;
                float cn = fg * cv + ig * gg;
                if (q == 0) co.x = cn; else co.y = cn;
                hv[q] = og * fmaxf(cn, 0.f);
            }
            *(float2*)&g_c[gm * H_SZ + hc] = co;
            // write fp16 pair straight into next step's A-frag layout
            int mt = gm >> 4, rowin = gm & 15, k16 = hc >> 4, kc = hc & 15;
            int gid = rowin & 7, r8 = rowin >> 3;
            int tig = (kc & 7) >> 1, khi = kc >> 3;
            int al  = gid * 4 + tig;
            int v   = r8 | (khi << 1);
            __half2 h2 = __halves2half2(__float2half(hv[0]), __float2half(hv[1]));
            an[mt * 8192 + k16 * 128 + al * 4 + v] = *(uint32_t*)&h2;
            if (t == T_SZ - 1)
                *(float2*)&g_hl[gm * H_SZ + hc] = make_float2(hv[0], hv[1]);
        }
        __syncthreads();
    }
}

// ---------------- dense head: y = h_T @ Wd + bd -----------------------------
__global__ void head_kernel(const float* __restrict__ Wd,
                            const float* __restrict__ bd,
                            float* __restrict__ out) {
    __shared__ float hs[H_SZ];
    const int row  = blockIdx.x;
    const int tid  = threadIdx.x;
    const int lane = tid & 31;
    const int w    = tid >> 5;
    for (int i = tid; i < H_SZ; i += 256) hs[i] = g_hl[row * H_SZ + i];
    __syncthreads();
    for (int o = w; o < OUT_SZ; o += 8) {
        float s = 0.f;
        for (int k = lane; k < H_SZ; k += 32) s += hs[k] * Wd[k * OUT_SZ + o];
#pragma unroll
        for (int off = 16; off; off >>= 1)
            s += __shfl_down_sync(0xffffffffu, s, off);
        if (lane == 0) out[row * OUT_SZ + o] = s + bd[o];
    }
}

extern "C" void kernel_launch(void* const* d_in, const int* in_sizes, int n_in,
                              void* d_out, int out_size) {
    const float* x    = (const float*)d_in[0];   // [2048,60,89]
    const float* W    = (const float*)d_in[1];   // [89,4096]
    const float* U    = (const float*)d_in[2];   // [1024,4096]
    const float* bias = (const float*)d_in[3];   // [4096]
    const float* Wd   = (const float*)d_in[4];   // [1024,30]
    const float* bd   = (const float*)d_in[5];   // [30]
    float* out = (float*)d_out;                  // [2048,30,1]

    pack_B<<<8960, 256>>>(U, W);
    pack_x<<<23040, 256>>>(x);
    zero_state<<<2048, 256>>>();

    dim3 grid(B_SZ / 128, H_SZ / 32);            // 16 x 32 CTAs
    for (int t = 0; t < T_SZ; t++)
        lstm_step<<<grid, 256>>>(bias, t);

    head_kernel<<<B_SZ, 256>>>(Wd, bd, out);
}

// round 14
// speedup vs baseline: 2.0773x; 1.0500x over previous
#include <cuda_runtime.h>
#include <cuda_fp16.h>
#include <cstdint>

#define B_SZ   2048
#define T_SZ   60
#define F_SZ   89
#define H_SZ   1024
#define OUT_SZ 30
#define NCH    18        // k-chunks of 64: 16 (h) + 2 (x, 89->128 padded)
#define HCHN   16
#define STAGES 3
#define STG_U32 8192     // 32KB per stage in u32 units (A 16KB | B 16KB)

// ---------------- persistent scratch (__device__ globals, no allocs) --------
// Apack: h fp16 pairs, m16n8k16 A-frag order [mt(128)][k16(64)][lane(32)][v(4)]
__device__ __align__(16) uint32_t g_ap0[128 * 64 * 32 * 4];
__device__ __align__(16) uint32_t g_ap1[128 * 64 * 32 * 4];
// Bpack: U|W fp16 B-frags [by(32)][ch(18)][k16(4)][nb16(8)][lane(32)][v(4)]
__device__ __align__(16) uint32_t g_bp[32 * 18 * 4 * 8 * 32 * 4];
// xpack: x fp16 A-frags [t(60)][mt(128)][k16x(8)][lane(32)][v(4)]
__device__ __align__(16) uint32_t g_xp[60 * 128 * 8 * 32 * 4];
__device__ float g_c [B_SZ * H_SZ];
__device__ float g_hl[B_SZ * H_SZ];

__device__ __forceinline__ void mma_f16(float (&d)[4], const uint4& a,
                                        uint32_t b0, uint32_t b1) {
    asm volatile(
        "mma.sync.aligned.m16n8k16.row.col.f32.f16.f16.f32 "
        "{%0,%1,%2,%3}, {%4,%5,%6,%7}, {%8,%9}, {%0,%1,%2,%3};"
        : "+f"(d[0]), "+f"(d[1]), "+f"(d[2]), "+f"(d[3])
        : "r"(a.x), "r"(a.y), "r"(a.z), "r"(a.w), "r"(b0), "r"(b1));
}

__device__ __forceinline__ void cp_async16(uint32_t saddr, const void* g) {
    asm volatile("cp.async.cg.shared.global [%0], [%1], 16;\n"
                 :: "r"(saddr), "l"(g));
}

// ---------------- prep kernels (run once per launch) ------------------------
__global__ void zero_state() {
    int gi = blockIdx.x * blockDim.x + threadIdx.x;
    int stride = gridDim.x * blockDim.x;
    for (int i = gi; i < 128 * 64 * 32 * 4; i += stride) g_ap0[i] = 0u;
    for (int i = gi; i < B_SZ * H_SZ; i += stride)       g_c[i]  = 0.f;
}

// B-frag for m16n8k16 (col-major B = [K,N], N = ncat gate strips):
// v = { n8lo klo, n8lo khi, n8hi klo, n8hi khi }, each u32 = fp16 pair (k, k+1)
__global__ void pack_B(const float* __restrict__ U, const float* __restrict__ W) {
    int idx = blockIdx.x * 256 + threadIdx.x;   // 32*73728 = 2,359,296 exact
    int by  = idx / 73728;
    int r   = idx % 73728;
    int ch  = r / 4096;
    int r2  = r & 4095;
    int k16 = r2 >> 10;
    int nb  = (r2 >> 7) & 7;
    int lane = (r2 >> 2) & 31;
    int v    = r2 & 3;
    int gid = lane >> 2, tig = lane & 3;
    int k    = ch * 64 + k16 * 16 + tig * 2 + (v & 1) * 8;
    int ncat = nb * 16 + (v >> 1) * 8 + gid;
    int uc   = (ncat >> 5) * H_SZ + by * 32 + (ncat & 31);
    float v0 = 0.f, v1 = 0.f;
    if (k < H_SZ)                 v0 = U[k * (4 * H_SZ) + uc];
    else if (k < H_SZ + F_SZ)     v0 = W[(k - H_SZ) * (4 * H_SZ) + uc];
    if (k + 1 < H_SZ)             v1 = U[(k + 1) * (4 * H_SZ) + uc];
    else if (k + 1 < H_SZ + F_SZ) v1 = W[(k + 1 - H_SZ) * (4 * H_SZ) + uc];
    __half2 h2 = __halves2half2(__float2half(v0), __float2half(v1));
    g_bp[idx] = *(uint32_t*)&h2;
}

// A-frag: v = { rlo klo, rhi klo, rlo khi, rhi khi }, u32 = fp16 pair (k, k+1)
__global__ void pack_x(const float* __restrict__ x) {
    int idx = blockIdx.x * 256 + threadIdx.x;   // 60*131072 = 7,864,320 exact
    int t   = idx / 131072;
    int r   = idx % 131072;
    int mt  = r / 1024;
    int r2  = r & 1023;
    int k16 = r2 >> 7;
    int lane = (r2 >> 2) & 31;
    int v    = r2 & 3;
    int gid = lane >> 2, tig = lane & 3;
    int row = mt * 16 + gid + (v & 1) * 8;
    int f   = k16 * 16 + tig * 2 + (v >> 1) * 8;
    float v0 = (f < F_SZ)     ? x[(row * T_SZ + t) * F_SZ + f]     : 0.f;
    float v1 = (f + 1 < F_SZ) ? x[(row * T_SZ + t) * F_SZ + f + 1] : 0.f;
    __half2 h2 = __halves2half2(__float2half(v0), __float2half(v1));
    g_xp[idx] = *(uint32_t*)&h2;
}

// ---------------- recurrent step: fp16 K64 cp.async pipelined GEMM ----------
__global__ __launch_bounds__(256, 2)
void lstm_step(const float* __restrict__ bias, int t) {
    const int bx = blockIdx.x, by = blockIdx.y;
    const int tid = threadIdx.x, lane = tid & 31, warp = tid >> 5;
    const int warpM = warp >> 1, warpN = warp & 1;

    const uint32_t* __restrict__ ap = (t & 1) ? g_ap1 : g_ap0;
    uint32_t*       __restrict__ an = (t & 1) ? g_ap0 : g_ap1;

    extern __shared__ __align__(16) uint32_t smdyn[];   // STAGES * 32KB
    float (*zs)[132] = (float (*)[132])smdyn;           // epilogue alias

    const int mtB = bx * 8;
    const uint32_t sbase = (uint32_t)__cvta_generic_to_shared(smdyn);
    const uint32_t sdst  = sbase + tid * 16;

    // ---- hoisted per-thread copy offsets (u32 element units) ----
    // A: 8 mt-blocks of 2KB per stage; thread copies 4 x 16B (A) + 4 x 16B (B)
    int aoffH[4], aoffX[4];
#pragma unroll
    for (int it = 0; it < 4; it++) {
        int idx = tid + it * 256;
        int b   = idx >> 7;              // 0..7 (mt local)
        int off = idx & 127;             // 16B units within 2KB block
        aoffH[it] = (mtB + b) * 8192 + off * 4;
        aoffX[it] = (t * 128 + mtB + b) * 1024 + off * 4;
    }
    const uint32_t* bThr = g_bp + by * 73728 + tid * 4;   // + c*4096 + it*1024

    auto issue = [&](int c, int s) {
        uint32_t sb = sdst + s * 32768;
        if (c < HCHN) {
            int adv = c * 512;
#pragma unroll
            for (int it = 0; it < 4; it++)
                cp_async16(sb + it * 4096, ap + aoffH[it] + adv);
        } else {
            int adv = (c - HCHN) * 512;
#pragma unroll
            for (int it = 0; it < 4; it++)
                cp_async16(sb + it * 4096, g_xp + aoffX[it] + adv);
        }
        const uint32_t* bsrc = bThr + c * 4096;
#pragma unroll
        for (int it = 0; it < 4; it++)
            cp_async16(sb + 16384 + it * 4096, bsrc + it * 1024);
    };

    float acc[2][8][4] = {};

#pragma unroll
    for (int s = 0; s < STAGES - 1; s++) {
        issue(s, s);
        asm volatile("cp.async.commit_group;");
    }

    int stage = 0;
    for (int c = 0; c < NCH; c++) {
        asm volatile("cp.async.wait_group %0;" :: "n"(STAGES - 2));
        __syncthreads();

        const uint32_t* sA = smdyn + stage * STG_U32;  // [mtl(8)][k16(4)][lane][v]
        const uint32_t* sB = sA + 4096;                // [k16(4)][nb16(8)][lane][v]
#pragma unroll
        for (int k16 = 0; k16 < 4; k16++) {
            uint4 aF[2];
#pragma unroll
            for (int mi = 0; mi < 2; mi++)
                aF[mi] = *(const uint4*)
                    &sA[((warpM * 2 + mi) * 4 + k16) * 128 + lane * 4];
#pragma unroll
            for (int j = 0; j < 4; j++) {
                uint4 b = *(const uint4*)
                    &sB[k16 * 1024 + (warpN * 4 + j) * 128 + lane * 4];
#pragma unroll
                for (int mi = 0; mi < 2; mi++) {
                    mma_f16(acc[mi][j * 2],     aF[mi], b.x, b.y);
                    mma_f16(acc[mi][j * 2 + 1], aF[mi], b.z, b.w);
                }
            }
        }

        int cn = c + STAGES - 1;
        if (cn < NCH) issue(cn, cn % STAGES);
        asm volatile("cp.async.commit_group;");
        if (++stage == STAGES) stage = 0;
    }
    __syncthreads();   // pipe buffers dead; zs aliases them

    // ---- fused gate epilogue (two 64-row halves through shared) ----
#pragma unroll
    for (int half = 0; half < 2; half++) {
        if ((warpM >> 1) == half) {
#pragma unroll
            for (int mi = 0; mi < 2; mi++) {
                int zr = (warpM & 1) * 32 + mi * 16 + (lane >> 2);
#pragma unroll
                for (int ni = 0; ni < 8; ni++) {
                    int cN = warpN * 64 + ni * 8 + (lane & 3) * 2;
                    zs[zr][cN]         = acc[mi][ni][0];
                    zs[zr][cN + 1]     = acc[mi][ni][1];
                    zs[zr + 8][cN]     = acc[mi][ni][2];
                    zs[zr + 8][cN + 1] = acc[mi][ni][3];
                }
            }
        }
        __syncthreads();
        // pairs: 64 rows x 16 col-pairs = 1024 items, 4 per thread
#pragma unroll
        for (int e = 0; e < 4; e++) {
            int idx = tid + e * 256;
            int m  = idx >> 4, np = idx & 15;
            int nl = np * 2;
            int gm = bx * 128 + half * 64 + m;
            int hc = by * 32 + nl;
            float2 co = *(float2*)&g_c[gm * H_SZ + hc];
            float hv[2];
#pragma unroll
            for (int q = 0; q < 2; q++) {
                int nn = nl + q;
                float zi = zs[m][nn]      + bias[hc + q];
                float zf = zs[m][32 + nn] + bias[H_SZ + hc + q];
                float zg = zs[m][64 + nn] + bias[2 * H_SZ + hc + q];
                float zo = zs[m][96 + nn] + bias[3 * H_SZ + hc + q];
                float ig = 1.f / (1.f + __expf(-zi));
                float fg = 1.f / (1.f + __expf(-zf));
                float gg = fmaxf(zg, 0.f);
                float og = 1.f / (1.f + __expf(-zo));
                float cv = (q == 0) ? co.x : co.y;
                float cn = fg * cv + ig * gg;
                if (q == 0) co.x = cn; else co.y = cn;
                hv[q] = og * fmaxf(cn, 0.f);
            }
            *(float2*)&g_c[gm * H_SZ + hc] = co;
            // write fp16 pair straight into next step's A-frag layout
            int mt = gm >> 4, rowin = gm & 15, k16 = hc >> 4, kc = hc & 15;
            int gid = rowin & 7, r8 = rowin >> 3;
            int tig = (kc & 7) >> 1, khi = kc >> 3;
            int al  = gid * 4 + tig;
            int v   = r8 | (khi << 1);
            __half2 h2 = __halves2half2(__float2half(hv[0]), __float2half(hv[1]));
            an[mt * 8192 + k16 * 128 + al * 4 + v] = *(uint32_t*)&h2;
            if (t == T_SZ - 1)
                *(float2*)&g_hl[gm * H_SZ + hc] = make_float2(hv[0], hv[1]);
        }
        __syncthreads();
    }
}

// ---------------- dense head: y = h_T @ Wd + bd -----------------------------
__global__ void head_kernel(const float* __restrict__ Wd,
                            const float* __restrict__ bd,
                            float* __restrict__ out) {
    __shared__ float hs[H_SZ];
    const int row  = blockIdx.x;
    const int tid  = threadIdx.x;
    const int lane = tid & 31;
    const int w    = tid >> 5;
    for (int i = tid; i < H_SZ; i += 256) hs[i] = g_hl[row * H_SZ + i];
    __syncthreads();
    for (int o = w; o < OUT_SZ; o += 8) {
        float s = 0.f;
        for (int k = lane; k < H_SZ; k += 32) s += hs[k] * Wd[k * OUT_SZ + o];
#pragma unroll
        for (int off = 16; off; off >>= 1)
            s += __shfl_down_sync(0xffffffffu, s, off);
        if (lane == 0) out[row * OUT_SZ + o] = s + bd[o];
    }
}

extern "C" void kernel_launch(void* const* d_in, const int* in_sizes, int n_in,
                              void* d_out, int out_size) {
    const float* x    = (const float*)d_in[0];   // [2048,60,89]
    const float* W    = (const float*)d_in[1];   // [89,4096]
    const float* U    = (const float*)d_in[2];   // [1024,4096]
    const float* bias = (const float*)d_in[3];   // [4096]
    const float* Wd   = (const float*)d_in[4];   // [1024,30]
    const float* bd   = (const float*)d_in[5];   // [30]
    float* out = (float*)d_out;                  // [2048,30,1]

    const int dynsm = STAGES * 32768;            // 96KB
    static bool attr_set = false;
    if (!attr_set) {
        cudaFuncSetAttribute(lstm_step,
                             cudaFuncAttributeMaxDynamicSharedMemorySize, dynsm);
        attr_set = true;
    }

    pack_B<<<9216, 256>>>(U, W);
    pack_x<<<30720, 256>>>(x);
    zero_state<<<2048, 256>>>();

    dim3 grid(B_SZ / 128, H_SZ / 32);            // 16 x 32 CTAs
    for (int t = 0; t < T_SZ; t++)
        lstm_step<<<grid, 256, dynsm>>>(bias, t);

    head_kernel<<<B_SZ, 256>>>(Wd, bd, out);
}

// round 15
// speedup vs baseline: 2.1362x; 1.0283x over previous
#include <cuda_runtime.h>
#include <cuda_fp16.h>
#include <cstdint>

#define B_SZ   2048
#define T_SZ   60
#define F_SZ   89
#define H_SZ   1024
#define OUT_SZ 30
#define NCH    18        // k-chunks of 64: 16 (h) + 2 (x, 89->128 padded)
#define HCHN   16
#define STAGES 3
#define STG_U32 8192     // 32KB per stage in u32 units (A 16KB | B 16KB)

// ---------------- persistent scratch (__device__ globals, no allocs) --------
// Apack: h fp16 pairs, m16n8k16 A-frag order [mt(128)][k16(64)][lane(32)][v(4)]
__device__ __align__(16) uint32_t g_ap0[128 * 64 * 32 * 4];
__device__ __align__(16) uint32_t g_ap1[128 * 64 * 32 * 4];
// Bpack: U|W fp16 B-frags [by(32)][ch(18)][k16(4)][nb16(8)][lane(32)][v(4)]
// ncat mapping is GATE-INTERLEAVED: ncat = hcp*32 + gate*8 + hcl
__device__ __align__(16) uint32_t g_bp[32 * 18 * 4 * 8 * 32 * 4];
// xpack: x fp16 A-frags [t(60)][mt(128)][k16x(8)][lane(32)][v(4)]
__device__ __align__(16) uint32_t g_xp[60 * 128 * 8 * 32 * 4];
__device__ float g_c [B_SZ * H_SZ];
__device__ float g_hl[B_SZ * H_SZ];

__device__ __forceinline__ void mma_f16(float (&d)[4], const uint4& a,
                                        uint32_t b0, uint32_t b1) {
    asm volatile(
        "mma.sync.aligned.m16n8k16.row.col.f32.f16.f16.f32 "
        "{%0,%1,%2,%3}, {%4,%5,%6,%7}, {%8,%9}, {%0,%1,%2,%3};"
        : "+f"(d[0]), "+f"(d[1]), "+f"(d[2]), "+f"(d[3])
        : "r"(a.x), "r"(a.y), "r"(a.z), "r"(a.w), "r"(b0), "r"(b1));
}

__device__ __forceinline__ void cp_async16(uint32_t saddr, const void* g) {
    asm volatile("cp.async.cg.shared.global [%0], [%1], 16;\n"
                 :: "r"(saddr), "l"(g));
}

// ---------------- prep kernels (run once per launch) ------------------------
__global__ void zero_state() {
    int gi = blockIdx.x * blockDim.x + threadIdx.x;
    int stride = gridDim.x * blockDim.x;
    for (int i = gi; i < 128 * 64 * 32 * 4; i += stride) g_ap0[i] = 0u;
    for (int i = gi; i < B_SZ * H_SZ; i += stride)       g_c[i]  = 0.f;
}

// B-frag for m16n8k16 (col-major B = [K,N]); gate-interleaved ncat:
//   hcp = ncat>>5 (8-col hc group), gate = (ncat>>3)&3, hcl = ncat&7
//   U/W column = gate*H + by*32 + hcp*8 + hcl
__global__ void pack_B(const float* __restrict__ U, const float* __restrict__ W) {
    int idx = blockIdx.x * 256 + threadIdx.x;   // 32*73728 = 2,359,296 exact
    int by  = idx / 73728;
    int r   = idx % 73728;
    int ch  = r / 4096;
    int r2  = r & 4095;
    int k16 = r2 >> 10;
    int nb  = (r2 >> 7) & 7;
    int lane = (r2 >> 2) & 31;
    int v    = r2 & 3;
    int gid = lane >> 2, tig = lane & 3;
    int k    = ch * 64 + k16 * 16 + tig * 2 + (v & 1) * 8;
    int ncat = nb * 16 + (v >> 1) * 8 + gid;
    int uc   = ((ncat >> 3) & 3) * H_SZ + by * 32 + (ncat >> 5) * 8 + (ncat & 7);
    float v0 = 0.f, v1 = 0.f;
    if (k < H_SZ)                 v0 = U[k * (4 * H_SZ) + uc];
    else if (k < H_SZ + F_SZ)     v0 = W[(k - H_SZ) * (4 * H_SZ) + uc];
    if (k + 1 < H_SZ)             v1 = U[(k + 1) * (4 * H_SZ) + uc];
    else if (k + 1 < H_SZ + F_SZ) v1 = W[(k + 1 - H_SZ) * (4 * H_SZ) + uc];
    __half2 h2 = __halves2half2(__float2half(v0), __float2half(v1));
    g_bp[idx] = *(uint32_t*)&h2;
}

// A-frag: v = { rlo klo, rhi klo, rlo khi, rhi khi }, u32 = fp16 pair (k, k+1)
__global__ void pack_x(const float* __restrict__ x) {
    int idx = blockIdx.x * 256 + threadIdx.x;   // 60*131072 = 7,864,320 exact
    int t   = idx / 131072;
    int r   = idx % 131072;
    int mt  = r / 1024;
    int r2  = r & 1023;
    int k16 = r2 >> 7;
    int lane = (r2 >> 2) & 31;
    int v    = r2 & 3;
    int gid = lane >> 2, tig = lane & 3;
    int row = mt * 16 + gid + (v & 1) * 8;
    int f   = k16 * 16 + tig * 2 + (v >> 1) * 8;
    float v0 = (f < F_SZ)     ? x[(row * T_SZ + t) * F_SZ + f]     : 0.f;
    float v1 = (f + 1 < F_SZ) ? x[(row * T_SZ + t) * F_SZ + f + 1] : 0.f;
    __half2 h2 = __halves2half2(__float2half(v0), __float2half(v1));
    g_xp[idx] = *(uint32_t*)&h2;
}

// ---------------- recurrent step: fp16 K64 pipelined GEMM, reg epilogue -----
__global__ __launch_bounds__(256, 2)
void lstm_step(const float* __restrict__ bias, int t) {
    const int bx = blockIdx.x, by = blockIdx.y;
    const int tid = threadIdx.x, lane = tid & 31, warp = tid >> 5;
    const int warpM = warp >> 1, warpN = warp & 1;

    const uint32_t* __restrict__ ap = (t & 1) ? g_ap1 : g_ap0;
    uint32_t*       __restrict__ an = (t & 1) ? g_ap0 : g_ap1;

    extern __shared__ __align__(16) uint32_t smdyn[];   // STAGES * 32KB

    const int mtB = bx * 8;
    const uint32_t sbase = (uint32_t)__cvta_generic_to_shared(smdyn);
    const uint32_t sdst  = sbase + tid * 16;

    // ---- hoisted per-thread copy offsets (u32 element units) ----
    int aoffH[4], aoffX[4];
#pragma unroll
    for (int it = 0; it < 4; it++) {
        int idx = tid + it * 256;
        int b   = idx >> 7;              // 0..7 (mt local)
        int off = idx & 127;             // 16B units within 2KB block
        aoffH[it] = (mtB + b) * 8192 + off * 4;
        aoffX[it] = (t * 128 + mtB + b) * 1024 + off * 4;
    }
    const uint32_t* bThr = g_bp + by * 73728 + tid * 4;   // + c*4096 + it*1024

    auto issue = [&](int c, int s) {
        uint32_t sb = sdst + s * 32768;
        if (c < HCHN) {
            int adv = c * 512;
#pragma unroll
            for (int it = 0; it < 4; it++)
                cp_async16(sb + it * 4096, ap + aoffH[it] + adv);
        } else {
            int adv = (c - HCHN) * 512;
#pragma unroll
            for (int it = 0; it < 4; it++)
                cp_async16(sb + it * 4096, g_xp + aoffX[it] + adv);
        }
        const uint32_t* bsrc = bThr + c * 4096;
#pragma unroll
        for (int it = 0; it < 4; it++)
            cp_async16(sb + 16384 + it * 4096, bsrc + it * 1024);
    };

    float acc[2][8][4] = {};

#pragma unroll
    for (int s = 0; s < STAGES - 1; s++) {
        issue(s, s);
        asm volatile("cp.async.commit_group;");
    }

    int stage = 0;
    for (int c = 0; c < NCH; c++) {
        asm volatile("cp.async.wait_group %0;" :: "n"(STAGES - 2));
        __syncthreads();

        const uint32_t* sA = smdyn + stage * STG_U32;  // [mtl(8)][k16(4)][lane][v]
        const uint32_t* sB = sA + 4096;                // [k16(4)][nb16(8)][lane][v]
#pragma unroll
        for (int k16 = 0; k16 < 4; k16++) {
            uint4 aF[2];
#pragma unroll
            for (int mi = 0; mi < 2; mi++)
                aF[mi] = *(const uint4*)
                    &sA[((warpM * 2 + mi) * 4 + k16) * 128 + lane * 4];
#pragma unroll
            for (int j = 0; j < 4; j++) {
                uint4 b = *(const uint4*)
                    &sB[k16 * 1024 + (warpN * 4 + j) * 128 + lane * 4];
#pragma unroll
                for (int mi = 0; mi < 2; mi++) {
                    mma_f16(acc[mi][j * 2],     aF[mi], b.x, b.y);
                    mma_f16(acc[mi][j * 2 + 1], aF[mi], b.z, b.w);
                }
            }
        }

        int cn = c + STAGES - 1;
        if (cn < NCH) issue(cn, cn % STAGES);
        asm volatile("cp.async.commit_group;");
        if (++stage == STAGES) stage = 0;
    }

    // ---- register-local fused gate epilogue (no smem, no barriers) ----
    // acc[mi][ni]: gate = ni&3, hcp_local = ni>>2 (gate-interleaved B layout)
    const int colq = (lane & 3) * 2;
#pragma unroll
    for (int mi = 0; mi < 2; mi++) {
#pragma unroll
        for (int hp = 0; hp < 2; hp++) {
            const int hc = by * 32 + (warpN * 2 + hp) * 8 + colq;  // even
            const float bi0 = bias[hc],              bi1 = bias[hc + 1];
            const float bf0 = bias[H_SZ + hc],       bf1 = bias[H_SZ + hc + 1];
            const float bg0 = bias[2 * H_SZ + hc],   bg1 = bias[2 * H_SZ + hc + 1];
            const float bo0 = bias[3 * H_SZ + hc],   bo1 = bias[3 * H_SZ + hc + 1];
#pragma unroll
            for (int rh = 0; rh < 2; rh++) {
                const int gm = bx * 128 + warpM * 32 + mi * 16 +
                               (lane >> 2) + rh * 8;
                float2 co = *(float2*)&g_c[gm * H_SZ + hc];
                float hv[2];
#pragma unroll
                for (int q = 0; q < 2; q++) {
                    const int vi = rh * 2 + q;
                    float zi = acc[mi][hp * 4 + 0][vi] + (q ? bi1 : bi0);
                    float zf = acc[mi][hp * 4 + 1][vi] + (q ? bf1 : bf0);
                    float zg = acc[mi][hp * 4 + 2][vi] + (q ? bg1 : bg0);
                    float zo = acc[mi][hp * 4 + 3][vi] + (q ? bo1 : bo0);
                    float ig = 1.f / (1.f + __expf(-zi));
                    float fg = 1.f / (1.f + __expf(-zf));
                    float gg = fmaxf(zg, 0.f);
                    float og = 1.f / (1.f + __expf(-zo));
                    float cv = q ? co.y : co.x;
                    float cn = fg * cv + ig * gg;
                    if (q) co.y = cn; else co.x = cn;
                    hv[q] = og * fmaxf(cn, 0.f);
                }
                *(float2*)&g_c[gm * H_SZ + hc] = co;
                // write fp16 pair straight into next step's A-frag layout
                int mt = gm >> 4, rowin = gm & 15, k16 = hc >> 4, kc = hc & 15;
                int gid = rowin & 7, r8 = rowin >> 3;
                int tig = (kc & 7) >> 1, khi = kc >> 3;
                int al  = gid * 4 + tig;
                int v   = r8 | (khi << 1);
                __half2 h2 = __halves2half2(__float2half(hv[0]),
                                            __float2half(hv[1]));
                an[mt * 8192 + k16 * 128 + al * 4 + v] = *(uint32_t*)&h2;
                if (t == T_SZ - 1)
                    *(float2*)&g_hl[gm * H_SZ + hc] = make_float2(hv[0], hv[1]);
            }
        }
    }
}

// ---------------- dense head: y = h_T @ Wd + bd -----------------------------
__global__ void head_kernel(const float* __restrict__ Wd,
                            const float* __restrict__ bd,
                            float* __restrict__ out) {
    __shared__ float hs[H_SZ];
    const int row  = blockIdx.x;
    const int tid  = threadIdx.x;
    const int lane = tid & 31;
    const int w    = tid >> 5;
    for (int i = tid; i < H_SZ; i += 256) hs[i] = g_hl[row * H_SZ + i];
    __syncthreads();
    for (int o = w; o < OUT_SZ; o += 8) {
        float s = 0.f;
        for (int k = lane; k < H_SZ; k += 32) s += hs[k] * Wd[k * OUT_SZ + o];
#pragma unroll
        for (int off = 16; off; off >>= 1)
            s += __shfl_down_sync(0xffffffffu, s, off);
        if (lane == 0) out[row * OUT_SZ + o] = s + bd[o];
    }
}

extern "C" void kernel_launch(void* const* d_in, const int* in_sizes, int n_in,
                              void* d_out, int out_size) {
    const float* x    = (const float*)d_in[0];   // [2048,60,89]
    const float* W    = (const float*)d_in[1];   // [89,4096]
    const float* U    = (const float*)d_in[2];   // [1024,4096]
    const float* bias = (const float*)d_in[3];   // [4096]
    const float* Wd   = (const float*)d_in[4];   // [1024,30]
    const float* bd   = (const float*)d_in[5];   // [30]
    float* out = (float*)d_out;                  // [2048,30,1]

    const int dynsm = STAGES * 32768;            // 96KB
    static bool attr_set = false;
    if (!attr_set) {
        cudaFuncSetAttribute(lstm_step,
                             cudaFuncAttributeMaxDynamicSharedMemorySize, dynsm);
        attr_set = true;
    }

    pack_B<<<9216, 256>>>(U, W);
    pack_x<<<30720, 256>>>(x);
    zero_state<<<2048, 256>>>();

    dim3 grid(B_SZ / 128, H_SZ / 32);            // 16 x 32 CTAs
    for (int t = 0; t < T_SZ; t++)
        lstm_step<<<grid, 256, dynsm>>>(bias, t);

    head_kernel<<<B_SZ, 256>>>(Wd, bd, out);
}